// round 14
// baseline (speedup 1.0000x reference)
#include <cuda_runtime.h>
#include <cuda_bf16.h>
#include <mma.h>
#include <math.h>
#include <stdint.h>

using namespace nvcuda;

#define BSZ  2
#define LSEQ 2048
#define EMB  1024
#define HN   16
#define DHD  64
#define DFF  4096
#define MR   (BSZ*LSEQ)
#define N3E  (3*EMB)

// ---------------------------------------------------------------------------
// Scratch
// ---------------------------------------------------------------------------
__device__ float g_bqkv[N3E];
__device__ float g_q  [(size_t)MR * EMB];
__device__ float g_t1 [(size_t)MR * EMB];
__device__ float g_h  [(size_t)MR * EMB];

__device__ __nv_bfloat16 g_kh [(size_t)MR * EMB], g_kl [(size_t)MR * EMB];
__device__ __nv_bfloat16 g_vh [(size_t)MR * EMB], g_vl [(size_t)MR * EMB];
__device__ __nv_bfloat16 g_xh [(size_t)MR * EMB], g_xl [(size_t)MR * EMB];
__device__ __nv_bfloat16 g_zh [(size_t)MR * EMB], g_zl [(size_t)MR * EMB];
__device__ __nv_bfloat16 g_hh [(size_t)MR * EMB], g_hl [(size_t)MR * EMB];
__device__ __nv_bfloat16 g_ffh[(size_t)MR * DFF], g_ffl[(size_t)MR * DFF];
__device__ __nv_bfloat16 g_wqkvh[(size_t)EMB * N3E], g_wqkvl[(size_t)EMB * N3E];
__device__ __nv_bfloat16 g_woh[(size_t)EMB * EMB],  g_wol[(size_t)EMB * EMB];
__device__ __nv_bfloat16 g_w1h[(size_t)EMB * DFF],  g_w1l[(size_t)EMB * DFF];
__device__ __nv_bfloat16 g_w2h[(size_t)DFF * EMB],  g_w2l[(size_t)DFF * EMB];

// ---------------------------------------------------------------------------
// helpers
// ---------------------------------------------------------------------------
__device__ __forceinline__ uint32_t smem_u32(const void* p) {
    uint32_t a;
    asm("{ .reg .u64 t; cvta.to.shared.u64 t, %1; cvt.u32.u64 %0, t; }" : "=r"(a) : "l"(p));
    return a;
}
#define CP_ASYNC(dst, src) asm volatile("cp.async.cg.shared.global [%0], [%1], 16;" :: "r"(dst), "l"(src))
#define CP_COMMIT()        asm volatile("cp.async.commit_group;" ::: "memory")
#define CP_WAIT(n)         asm volatile("cp.async.wait_group %0;" :: "n"(n) : "memory")

__device__ __forceinline__ void split2(float v, __nv_bfloat16& h, __nv_bfloat16& l) {
    h = __float2bfloat16(v);
    l = __float2bfloat16(v - __bfloat162float(h));
}

// ---------------------------------------------------------------------------
// fp32 -> bf16 hi/lo split (elementwise)
// ---------------------------------------------------------------------------
__global__ void split_kernel(const float* __restrict__ src, __nv_bfloat16* __restrict__ h,
                             __nv_bfloat16* __restrict__ l, int n4)
{
    int i = blockIdx.x * blockDim.x + threadIdx.x;
    if (i >= n4) return;
    float4 v = ((const float4*)src)[i];
    __nv_bfloat162 h01, h23, l01, l23;
    split2(v.x, h01.x, l01.x); split2(v.y, h01.y, l01.y);
    split2(v.z, h23.x, l23.x); split2(v.w, h23.y, l23.y);
    uint2 hv, lv;
    hv.x = *(uint32_t*)&h01; hv.y = *(uint32_t*)&h23;
    lv.x = *(uint32_t*)&l01; lv.y = *(uint32_t*)&l23;
    ((uint2*)h)[i] = hv;
    ((uint2*)l)[i] = lv;
}

__global__ void pack_qkv_split(const float* __restrict__ Wq, const float* __restrict__ Wk,
                               const float* __restrict__ Wv, const float* __restrict__ bq,
                               const float* __restrict__ bk, const float* __restrict__ bv)
{
    int idx = blockIdx.x * blockDim.x + threadIdx.x;
    if (idx < EMB * N3E) {
        int n = idx % N3E, e = idx / N3E;
        int proj = n / EMB, hd = n % EMB;
        const float* W = (proj == 0) ? Wq : (proj == 1) ? Wk : Wv;
        float v = W[(size_t)(hd >> 6) * EMB * DHD + (size_t)e * DHD + (hd & 63)];
        __nv_bfloat16 h, l; split2(v, h, l);
        g_wqkvh[idx] = h; g_wqkvl[idx] = l;
    }
    if (idx < N3E) {
        int proj = idx / EMB, hd = idx % EMB;
        const float* bb = (proj == 0) ? bq : (proj == 1) ? bk : bv;
        g_bqkv[idx] = bb[hd];
    }
}

// ---------------------------------------------------------------------------
// bf16x3 WMMA GEMM, cp.async 2-stage, 3 CTAs/SM. CTA 128x128, BK=32,
// 128 thr (2x2 warps), warp tile 64x64.
// MODE: 1 = f32 C = acc+bias+res; 2 = bf16 hi/lo split of relu(acc+bias);
//       3 = qkv: proj0 -> f32 C, proj1 -> Chi/Clo, proj2 -> Ch2/Cl2 (width 1024)
// ---------------------------------------------------------------------------
#define STG       37888
#define GEMM_SMEM (2 * STG)

__device__ __forceinline__ void issue_tile(uint32_t sbase,
    const __nv_bfloat16* __restrict__ Ah, const __nv_bfloat16* __restrict__ Al,
    const __nv_bfloat16* __restrict__ Bh, const __nv_bfloat16* __restrict__ Bl,
    int K, int N, int m0, int n0, int kt, int tid)
{
    const __nv_bfloat16* pah = Ah + (size_t)(m0 + tid) * K + kt;
    const __nv_bfloat16* pal = Al + (size_t)(m0 + tid) * K + kt;
    uint32_t da  = sbase + tid * 80;
    uint32_t dal = sbase + 10240 + tid * 80;
#pragma unroll
    for (int i = 0; i < 4; ++i) CP_ASYNC(da  + i * 16, pah + i * 8);
#pragma unroll
    for (int i = 0; i < 4; ++i) CP_ASYNC(dal + i * 16, pal + i * 8);
    int br = tid >> 2, bc = tid & 3;
    const __nv_bfloat16* pbh = Bh + (size_t)(kt + br) * N + n0 + bc * 8;
    const __nv_bfloat16* pbl = Bl + (size_t)(kt + br) * N + n0 + bc * 8;
    uint32_t db  = sbase + 20480 + br * 272 + bc * 16;
    uint32_t dbl = sbase + 29184 + br * 272 + bc * 16;
#pragma unroll
    for (int i = 0; i < 4; ++i) CP_ASYNC(db  + i * 64, pbh + i * 32);
#pragma unroll
    for (int i = 0; i < 4; ++i) CP_ASYNC(dbl + i * 64, pbl + i * 32);
}

template<int MODE>
__global__ __launch_bounds__(128, 3)
void bgemm(const __nv_bfloat16* __restrict__ Ah, const __nv_bfloat16* __restrict__ Al,
           const __nv_bfloat16* __restrict__ Bh, const __nv_bfloat16* __restrict__ Bl,
           const float* __restrict__ bias, const float* __restrict__ res,
           float* __restrict__ C, __nv_bfloat16* __restrict__ Chi,
           __nv_bfloat16* __restrict__ Clo, __nv_bfloat16* __restrict__ Ch2,
           __nv_bfloat16* __restrict__ Cl2, int M, int N, int K)
{
    extern __shared__ char smem[];
    const uint32_t sb = smem_u32(smem);
    const int tid = threadIdx.x;
    const int wid = tid >> 5;
    const int wm = wid >> 1, wn = wid & 1;
    const int bx = blockIdx.x, by = blockIdx.y;
    const int m0 = by * 128, n0 = bx * 128;
    const int NT = K / 32;

    wmma::fragment<wmma::accumulator, 16, 16, 16, float> acc[4][4];
#pragma unroll
    for (int i = 0; i < 4; ++i)
#pragma unroll
        for (int j = 0; j < 4; ++j) wmma::fill_fragment(acc[i][j], 0.f);

#pragma unroll
    for (int s = 0; s < 2; ++s) {
        issue_tile(sb + s * STG, Ah, Al, Bh, Bl, K, N, m0, n0, s * 32, tid);
        CP_COMMIT();
    }

    for (int t = 0; t < NT; ++t) {
        CP_WAIT(1);
        __syncthreads();

        const int buf = t & 1;
        const __nv_bfloat16* AHs = (const __nv_bfloat16*)(smem + buf * STG);
        const __nv_bfloat16* ALs = (const __nv_bfloat16*)(smem + buf * STG + 10240);
        const __nv_bfloat16* BHs = (const __nv_bfloat16*)(smem + buf * STG + 20480);
        const __nv_bfloat16* BLs = (const __nv_bfloat16*)(smem + buf * STG + 29184);

#pragma unroll
        for (int ks = 0; ks < 2; ++ks) {
            wmma::fragment<wmma::matrix_a, 16, 16, 16, __nv_bfloat16, wmma::row_major> fah[4], fal[4];
#pragma unroll
            for (int i = 0; i < 4; ++i) {
                int off = (wm * 64 + i * 16) * 40 + ks * 16;
                wmma::load_matrix_sync(fah[i], AHs + off, 40);
                wmma::load_matrix_sync(fal[i], ALs + off, 40);
            }
#pragma unroll
            for (int j = 0; j < 4; ++j) {
                wmma::fragment<wmma::matrix_b, 16, 16, 16, __nv_bfloat16, wmma::row_major> fbh, fbl;
                int off = (ks * 16) * 136 + wn * 64 + j * 16;
                wmma::load_matrix_sync(fbh, BHs + off, 136);
                wmma::load_matrix_sync(fbl, BLs + off, 136);
#pragma unroll
                for (int i = 0; i < 4; ++i) {
                    wmma::mma_sync(acc[i][j], fah[i], fbh, acc[i][j]);
                    wmma::mma_sync(acc[i][j], fah[i], fbl, acc[i][j]);
                    wmma::mma_sync(acc[i][j], fal[i], fbh, acc[i][j]);
                }
            }
        }

        __syncthreads();
        if (t + 2 < NT)
            issue_tile(sb + buf * STG, Ah, Al, Bh, Bl, K, N, m0, n0, (t + 2) * 32, tid);
        CP_COMMIT();
    }

    CP_WAIT(0);
    __syncthreads();

    float* Cs = (float*)smem;
    float* wbase = Cs + wid * 4352;
#pragma unroll
    for (int i = 0; i < 4; ++i)
#pragma unroll
        for (int j = 0; j < 4; ++j)
            wmma::store_matrix_sync(wbase + (i * 16) * 68 + j * 16, acc[i][j], 68,
                                    wmma::mem_row_major);
    __syncthreads();

    {
        const int m = m0 + tid;
        const float* bp = bias + n0;
        const float* rp = (MODE == 1) ? (res + (size_t)m * N + n0) : nullptr;
        const int proj = (MODE == 3) ? (n0 >> 10) : 0;
        const int colb = (MODE == 3) ? (n0 & 1023) : 0;
#pragma unroll 8
        for (int cb = 0; cb < 128; cb += 4) {
            int w = ((tid >> 6) << 1) | (cb >> 6);
            const float* sp = Cs + w * 4352 + (tid & 63) * 68 + (cb & 63);
            float4 v = *(const float4*)sp;
            float4 bi = *(const float4*)(bp + cb);
            v.x += bi.x; v.y += bi.y; v.z += bi.z; v.w += bi.w;
            if (MODE == 1) {
                float4 rr = *(const float4*)(rp + cb);
                v.x += rr.x; v.y += rr.y; v.z += rr.z; v.w += rr.w;
            }
            if (MODE == 2) {
                v.x = fmaxf(v.x, 0.f); v.y = fmaxf(v.y, 0.f);
                v.z = fmaxf(v.z, 0.f); v.w = fmaxf(v.w, 0.f);
            }
            if (MODE == 2 || (MODE == 3 && proj != 0)) {
                __nv_bfloat162 h01, h23, l01, l23;
                split2(v.x, h01.x, l01.x); split2(v.y, h01.y, l01.y);
                split2(v.z, h23.x, l23.x); split2(v.w, h23.y, l23.y);
                uint2 hv, lv;
                hv.x = *(uint32_t*)&h01; hv.y = *(uint32_t*)&h23;
                lv.x = *(uint32_t*)&l01; lv.y = *(uint32_t*)&l23;
                if (MODE == 2) {
                    *(uint2*)&Chi[(size_t)m * N + n0 + cb] = hv;
                    *(uint2*)&Clo[(size_t)m * N + n0 + cb] = lv;
                } else {
                    __nv_bfloat16* H = (proj == 1) ? Chi : Ch2;
                    __nv_bfloat16* L = (proj == 1) ? Clo : Cl2;
                    *(uint2*)&H[(size_t)m * 1024 + colb + cb] = hv;
                    *(uint2*)&L[(size_t)m * 1024 + colb + cb] = lv;
                }
            } else if (MODE == 3) {
                *(float4*)&C[(size_t)m * 1024 + colb + cb] = v;
            } else {
                *(float4*)&C[(size_t)m * N + n0 + cb] = v;
            }
        }
    }
}

// ---------------------------------------------------------------------------
// LayerNorm (optional split output)
// ---------------------------------------------------------------------------
__device__ __forceinline__ float block_sum_1024(float v, float* red)
{
#pragma unroll
    for (int o = 16; o; o >>= 1) v += __shfl_xor_sync(0xffffffffu, v, o);
    int w = threadIdx.x >> 5;
    if ((threadIdx.x & 31) == 0) red[w] = v;
    __syncthreads();
    if (threadIdx.x < 32) {
        float t = (threadIdx.x < 8) ? red[threadIdx.x] : 0.f;
#pragma unroll
        for (int o = 4; o; o >>= 1) t += __shfl_xor_sync(0xffffffffu, t, o);
        if (threadIdx.x == 0) red[0] = t;
    }
    __syncthreads();
    float r = red[0];
    __syncthreads();
    return r;
}

template<bool SPLIT>
__global__ __launch_bounds__(256)
void layernorm_kernel(const float* __restrict__ in, const float* __restrict__ g,
                      const float* __restrict__ beta, float* __restrict__ out,
                      __nv_bfloat16* __restrict__ oh, __nv_bfloat16* __restrict__ ol)
{
    __shared__ float red[8];
    const int row = blockIdx.x;
    const int tid = threadIdx.x;
    float4 v = ((const float4*)(in + (size_t)row * EMB))[tid];
    float mean = block_sum_1024(v.x + v.y + v.z + v.w, red) * (1.f / EMB);
    float dx = v.x - mean, dy = v.y - mean, dz = v.z - mean, dw = v.w - mean;
    float var = block_sum_1024(dx * dx + dy * dy + dz * dz + dw * dw, red) * (1.f / EMB);
    float rstd = rsqrtf(var + 1e-5f);
    float4 gv = ((const float4*)g)[tid];
    float4 bv = ((const float4*)beta)[tid];
    float4 o;
    o.x = dx * rstd * gv.x + bv.x;
    o.y = dy * rstd * gv.y + bv.y;
    o.z = dz * rstd * gv.z + bv.z;
    o.w = dw * rstd * gv.w + bv.w;
    ((float4*)(out + (size_t)row * EMB))[tid] = o;
    if (SPLIT) {
        __nv_bfloat162 h01, h23, l01, l23;
        split2(o.x, h01.x, l01.x); split2(o.y, h01.y, l01.y);
        split2(o.z, h23.x, l23.x); split2(o.w, h23.y, l23.y);
        uint2 hv, lv;
        hv.x = *(uint32_t*)&h01; hv.y = *(uint32_t*)&h23;
        lv.x = *(uint32_t*)&l01; lv.y = *(uint32_t*)&l23;
        ((uint2*)(oh + (size_t)row * EMB))[tid] = hv;
        ((uint2*)(ol + (size_t)row * EMB))[tid] = lv;
    }
}

// ---------------------------------------------------------------------------
// WMMA causal flash attention (unchanged from R12)
// ---------------------------------------------------------------------------
struct ASmem {
    __nv_bfloat16 Qh[64*72], Ql[64*72], Kh[64*72], Kl[64*72];
    __nv_bfloat16 Vh[64*72], Vl[64*72], Ph[64*72], Pl[64*72];
    float Ss[64*72];
    float Os[64*72];
    float mrow[64], lrow[64], arow[64];
    float pm[4*65], ps[4*65];
};

__global__ __launch_bounds__(256, 2)
void attn_wmma(const float* __restrict__ q,
               const __nv_bfloat16* __restrict__ kh, const __nv_bfloat16* __restrict__ kl,
               const __nv_bfloat16* __restrict__ vh, const __nv_bfloat16* __restrict__ vl,
               __nv_bfloat16* __restrict__ zh, __nv_bfloat16* __restrict__ zl)
{
    extern __shared__ char raw[];
    ASmem& sm = *reinterpret_cast<ASmem*>(raw);

    const int qb = blockIdx.x, h = blockIdx.y, b = blockIdx.z;
    const int tid = threadIdx.x, wid = tid >> 5;
    const int wy = wid >> 1, wx = wid & 1;
    const int r = tid >> 2, sg = tid & 3, c0 = sg * 16;

    {
        const float* qp = q + (size_t)(b * LSEQ + qb * 64 + r) * EMB + h * 64 + c0;
#pragma unroll
        for (int i = 0; i < 4; ++i) {
            float4 v = *(const float4*)(qp + i * 4);
            v.x *= 0.125f; v.y *= 0.125f; v.z *= 0.125f; v.w *= 0.125f;
            split2(v.x, sm.Qh[r*72 + c0 + i*4 + 0], sm.Ql[r*72 + c0 + i*4 + 0]);
            split2(v.y, sm.Qh[r*72 + c0 + i*4 + 1], sm.Ql[r*72 + c0 + i*4 + 1]);
            split2(v.z, sm.Qh[r*72 + c0 + i*4 + 2], sm.Ql[r*72 + c0 + i*4 + 2]);
            split2(v.w, sm.Qh[r*72 + c0 + i*4 + 3], sm.Ql[r*72 + c0 + i*4 + 3]);
            *(float4*)&sm.Os[r*72 + c0 + i*4] = make_float4(0.f, 0.f, 0.f, 0.f);
        }
    }
    if (tid < 64) { sm.mrow[tid] = -1e30f; sm.lrow[tid] = 0.f; }

    for (int kb = 0; kb <= qb; ++kb) {
        __syncthreads();
        {
            size_t go = (size_t)(b * LSEQ + kb * 64 + r) * EMB + h * 64 + c0;
            *(uint4*)&sm.Kh[r*72 + c0]     = *(const uint4*)(kh + go);
            *(uint4*)&sm.Kh[r*72 + c0 + 8] = *(const uint4*)(kh + go + 8);
            *(uint4*)&sm.Kl[r*72 + c0]     = *(const uint4*)(kl + go);
            *(uint4*)&sm.Kl[r*72 + c0 + 8] = *(const uint4*)(kl + go + 8);
            *(uint4*)&sm.Vh[r*72 + c0]     = *(const uint4*)(vh + go);
            *(uint4*)&sm.Vh[r*72 + c0 + 8] = *(const uint4*)(vh + go + 8);
            *(uint4*)&sm.Vl[r*72 + c0]     = *(const uint4*)(vl + go);
            *(uint4*)&sm.Vl[r*72 + c0 + 8] = *(const uint4*)(vl + go + 8);
        }
        __syncthreads();

        {
            wmma::fragment<wmma::accumulator, 16, 16, 16, float> s[2];
            wmma::fill_fragment(s[0], 0.f);
            wmma::fill_fragment(s[1], 0.f);
#pragma unroll
            for (int kk = 0; kk < 4; ++kk) {
                wmma::fragment<wmma::matrix_a, 16, 16, 16, __nv_bfloat16, wmma::row_major> fah, fal;
                wmma::load_matrix_sync(fah, &sm.Qh[(wy*16)*72 + kk*16], 72);
                wmma::load_matrix_sync(fal, &sm.Ql[(wy*16)*72 + kk*16], 72);
#pragma unroll
                for (int j = 0; j < 2; ++j) {
                    wmma::fragment<wmma::matrix_b, 16, 16, 16, __nv_bfloat16, wmma::col_major> fbh, fbl;
                    wmma::load_matrix_sync(fbh, &sm.Kh[(wx*32 + j*16)*72 + kk*16], 72);
                    wmma::load_matrix_sync(fbl, &sm.Kl[(wx*32 + j*16)*72 + kk*16], 72);
                    wmma::mma_sync(s[j], fah, fbh, s[j]);
                    wmma::mma_sync(s[j], fah, fbl, s[j]);
                    wmma::mma_sync(s[j], fal, fbh, s[j]);
                }
            }
            wmma::store_matrix_sync(&sm.Ss[(wy*16)*72 + wx*32],      s[0], 72, wmma::mem_row_major);
            wmma::store_matrix_sync(&sm.Ss[(wy*16)*72 + wx*32 + 16], s[1], 72, wmma::mem_row_major);
        }
        __syncthreads();

        const bool diag = (kb == qb);
        {
            float mx = -1e30f;
#pragma unroll
            for (int c = 0; c < 16; ++c) {
                float sv = sm.Ss[r*72 + c0 + c];
                if (diag && (c0 + c > r)) sv = -1e30f;
                mx = fmaxf(mx, sv);
            }
            sm.pm[sg*65 + r] = mx;
        }
        __syncthreads();
        if (sg == 0) {
            float mo = sm.mrow[r];
            float mn = fmaxf(fmaxf(sm.pm[r], sm.pm[65 + r]),
                             fmaxf(sm.pm[130 + r], sm.pm[195 + r]));
            mn = fmaxf(mn, mo);
            sm.arow[r] = __expf(mo - mn);
            sm.mrow[r] = mn;
        }
        __syncthreads();
        {
            float mn = sm.mrow[r];
            float psum = 0.f;
#pragma unroll
            for (int c = 0; c < 16; ++c) {
                float sv = sm.Ss[r*72 + c0 + c];
                float p = (diag && (c0 + c > r)) ? 0.f : __expf(sv - mn);
                split2(p, sm.Ph[r*72 + c0 + c], sm.Pl[r*72 + c0 + c]);
                psum += p;
            }
            sm.ps[sg*65 + r] = psum;
        }
        __syncthreads();
        if (sg == 0)
            sm.lrow[r] = sm.lrow[r] * sm.arow[r]
                       + sm.ps[r] + sm.ps[65 + r] + sm.ps[130 + r] + sm.ps[195 + r];

        {
            wmma::fragment<wmma::accumulator, 16, 16, 16, float> o[2];
            wmma::fill_fragment(o[0], 0.f);
            wmma::fill_fragment(o[1], 0.f);
#pragma unroll
            for (int kk = 0; kk < 4; ++kk) {
                wmma::fragment<wmma::matrix_a, 16, 16, 16, __nv_bfloat16, wmma::row_major> pah, pal;
                wmma::load_matrix_sync(pah, &sm.Ph[(wy*16)*72 + kk*16], 72);
                wmma::load_matrix_sync(pal, &sm.Pl[(wy*16)*72 + kk*16], 72);
#pragma unroll
                for (int j = 0; j < 2; ++j) {
                    wmma::fragment<wmma::matrix_b, 16, 16, 16, __nv_bfloat16, wmma::row_major> vbh, vbl;
                    wmma::load_matrix_sync(vbh, &sm.Vh[(kk*16)*72 + wx*32 + j*16], 72);
                    wmma::load_matrix_sync(vbl, &sm.Vl[(kk*16)*72 + wx*32 + j*16], 72);
                    wmma::mma_sync(o[j], pah, vbh, o[j]);
                    wmma::mma_sync(o[j], pah, vbl, o[j]);
                    wmma::mma_sync(o[j], pal, vbh, o[j]);
                }
            }
            wmma::store_matrix_sync(&sm.Ss[(wy*16)*72 + wx*32],      o[0], 72, wmma::mem_row_major);
            wmma::store_matrix_sync(&sm.Ss[(wy*16)*72 + wx*32 + 16], o[1], 72, wmma::mem_row_major);
        }
        __syncthreads();

        {
            float al = sm.arow[r];
#pragma unroll
            for (int i = 0; i < 4; ++i) {
                float4 ov = *(float4*)&sm.Os[r*72 + c0 + i*4];
                float4 pv = *(const float4*)&sm.Ss[r*72 + c0 + i*4];
                ov.x = ov.x * al + pv.x; ov.y = ov.y * al + pv.y;
                ov.z = ov.z * al + pv.z; ov.w = ov.w * al + pv.w;
                *(float4*)&sm.Os[r*72 + c0 + i*4] = ov;
            }
        }
    }
    __syncthreads();

    {
        float inv = 1.f / sm.lrow[r];
        uint32_t hp[8], lp[8];
#pragma unroll
        for (int cc = 0; cc < 8; ++cc) {
            float v0 = sm.Os[r*72 + c0 + cc*2]     * inv;
            float v1 = sm.Os[r*72 + c0 + cc*2 + 1] * inv;
            __nv_bfloat162 h2, l2;
            split2(v0, h2.x, l2.x);
            split2(v1, h2.y, l2.y);
            hp[cc] = *(uint32_t*)&h2;
            lp[cc] = *(uint32_t*)&l2;
        }
        size_t off = (size_t)(b * LSEQ + qb * 64 + r) * EMB + h * 64 + c0;
        *(uint4*)&zh[off]     = make_uint4(hp[0], hp[1], hp[2], hp[3]);
        *(uint4*)&zh[off + 8] = make_uint4(hp[4], hp[5], hp[6], hp[7]);
        *(uint4*)&zl[off]     = make_uint4(lp[0], lp[1], lp[2], lp[3]);
        *(uint4*)&zl[off + 8] = make_uint4(lp[4], lp[5], lp[6], lp[7]);
    }
}

// ---------------------------------------------------------------------------
// Launch
// ---------------------------------------------------------------------------
extern "C" void kernel_launch(void* const* d_in, const int* in_sizes, int n_in,
                              void* d_out, int out_size)
{
    const float* x   = (const float*)d_in[0];
    const float* Wq  = (const float*)d_in[2];
    const float* bq  = (const float*)d_in[3];
    const float* Wk  = (const float*)d_in[4];
    const float* bk  = (const float*)d_in[5];
    const float* Wv  = (const float*)d_in[6];
    const float* bv  = (const float*)d_in[7];
    const float* Wo  = (const float*)d_in[8];
    const float* bo  = (const float*)d_in[9];
    const float* W1  = (const float*)d_in[10];
    const float* c1  = (const float*)d_in[11];
    const float* W2  = (const float*)d_in[12];
    const float* c2  = (const float*)d_in[13];
    const float* g1  = (const float*)d_in[14];
    const float* be1 = (const float*)d_in[15];
    const float* g2  = (const float*)d_in[16];
    const float* be2 = (const float*)d_in[17];
    float* out = (float*)d_out;

    float *bqkv, *qbuf, *t1, *hbuf;
    __nv_bfloat16 *kh, *kl, *vh, *vl, *xh, *xl, *zh, *zl, *hh, *hl, *ffh, *ffl;
    __nv_bfloat16 *wqh, *wql, *woh, *wol, *w1h, *w1l, *w2h, *w2l;
    cudaGetSymbolAddress((void**)&bqkv, g_bqkv);
    cudaGetSymbolAddress((void**)&qbuf, g_q);
    cudaGetSymbolAddress((void**)&t1,   g_t1);
    cudaGetSymbolAddress((void**)&hbuf, g_h);
    cudaGetSymbolAddress((void**)&kh, g_kh); cudaGetSymbolAddress((void**)&kl, g_kl);
    cudaGetSymbolAddress((void**)&vh, g_vh); cudaGetSymbolAddress((void**)&vl, g_vl);
    cudaGetSymbolAddress((void**)&xh, g_xh); cudaGetSymbolAddress((void**)&xl, g_xl);
    cudaGetSymbolAddress((void**)&zh, g_zh); cudaGetSymbolAddress((void**)&zl, g_zl);
    cudaGetSymbolAddress((void**)&hh, g_hh); cudaGetSymbolAddress((void**)&hl, g_hl);
    cudaGetSymbolAddress((void**)&ffh, g_ffh); cudaGetSymbolAddress((void**)&ffl, g_ffl);
    cudaGetSymbolAddress((void**)&wqh, g_wqkvh); cudaGetSymbolAddress((void**)&wql, g_wqkvl);
    cudaGetSymbolAddress((void**)&woh, g_woh);   cudaGetSymbolAddress((void**)&wol, g_wol);
    cudaGetSymbolAddress((void**)&w1h, g_w1h);   cudaGetSymbolAddress((void**)&w1l, g_w1l);
    cudaGetSymbolAddress((void**)&w2h, g_w2h);   cudaGetSymbolAddress((void**)&w2l, g_w2l);

    cudaFuncSetAttribute(attn_wmma, cudaFuncAttributeMaxDynamicSharedMemorySize,
                         (int)sizeof(ASmem));
    cudaFuncSetAttribute(bgemm<1>, cudaFuncAttributeMaxDynamicSharedMemorySize, GEMM_SMEM);
    cudaFuncSetAttribute(bgemm<2>, cudaFuncAttributeMaxDynamicSharedMemorySize, GEMM_SMEM);
    cudaFuncSetAttribute(bgemm<3>, cudaFuncAttributeMaxDynamicSharedMemorySize, GEMM_SMEM);

    // conversions
    pack_qkv_split<<<(EMB * N3E + 255) / 256, 256>>>(Wq, Wk, Wv, bq, bk, bv);
    split_kernel<<<(EMB * EMB / 4 + 255) / 256, 256>>>(Wo, woh, wol, EMB * EMB / 4);
    split_kernel<<<(EMB * DFF / 4 + 255) / 256, 256>>>(W1, w1h, w1l, EMB * DFF / 4);
    split_kernel<<<(DFF * EMB / 4 + 255) / 256, 256>>>(W2, w2h, w2l, DFF * EMB / 4);
    split_kernel<<<(MR * EMB / 4 + 255) / 256, 256>>>(x, xh, xl, MR * EMB / 4);

    // qkv: q -> f32, k/v -> bf16 hi/lo splits
    bgemm<3><<<dim3(N3E / 128, MR / 128), 128, GEMM_SMEM>>>(
        xh, xl, wqh, wql, bqkv, nullptr, qbuf, kh, kl, vh, vl, MR, N3E, EMB);

    // attention -> zh/zl
    attn_wmma<<<dim3(LSEQ / 64, HN, BSZ), 256, sizeof(ASmem)>>>(
        qbuf, kh, kl, vh, vl, zh, zl);

    // t1 = z @ Wo + bo + x
    bgemm<1><<<dim3(EMB / 128, MR / 128), 128, GEMM_SMEM>>>(
        zh, zl, woh, wol, bo, x, t1, nullptr, nullptr, nullptr, nullptr, MR, EMB, EMB);

    // h = LN1(t1) + split
    layernorm_kernel<true><<<MR, 256>>>(t1, g1, be1, hbuf, hh, hl);

    // ff = relu(h @ W1 + c1) -> ffh/ffl
    bgemm<2><<<dim3(DFF / 128, MR / 128), 128, GEMM_SMEM>>>(
        hh, hl, w1h, w1l, c1, nullptr, nullptr, ffh, ffl, nullptr, nullptr, MR, DFF, EMB);

    // t1 = ff @ W2 + c2 + h
    bgemm<1><<<dim3(EMB / 128, MR / 128), 128, GEMM_SMEM>>>(
        ffh, ffl, w2h, w2l, c2, hbuf, t1, nullptr, nullptr, nullptr, nullptr, MR, EMB, DFF);

    // out = LN2(t1)
    layernorm_kernel<false><<<MR, 256>>>(t1, g2, be2, out, nullptr, nullptr);
}

// round 15
// speedup vs baseline: 1.0623x; 1.0623x over previous
#include <cuda_runtime.h>
#include <mma.h>
#include <math.h>
#include <stdint.h>

using namespace nvcuda;

#define BSZ  2
#define LSEQ 2048
#define EMB  1024
#define HN   16
#define DHD  64
#define DFF  4096
#define MR   (BSZ*LSEQ)
#define N3E  (3*EMB)

// ---------------------------------------------------------------------------
// Scratch (all fp32 now — TF32 path needs no split buffers)
// ---------------------------------------------------------------------------
__device__ float g_wqkv[(size_t)EMB * N3E];
__device__ float g_bqkv[N3E];
__device__ float g_qkv[(size_t)MR * N3E];
__device__ float g_z  [(size_t)MR * EMB];
__device__ float g_t1 [(size_t)MR * EMB];
__device__ float g_h  [(size_t)MR * EMB];
__device__ float g_ff [(size_t)MR * DFF];

// ---------------------------------------------------------------------------
// helpers
// ---------------------------------------------------------------------------
__device__ __forceinline__ uint32_t smem_u32(const void* p) {
    uint32_t a;
    asm("{ .reg .u64 t; cvta.to.shared.u64 t, %1; cvt.u32.u64 %0, t; }" : "=r"(a) : "l"(p));
    return a;
}
#define CP_ASYNC(dst, src) asm volatile("cp.async.cg.shared.global [%0], [%1], 16;" :: "r"(dst), "l"(src))
#define CP_COMMIT()        asm volatile("cp.async.commit_group;" ::: "memory")
#define CP_WAIT(n)         asm volatile("cp.async.wait_group %0;" :: "n"(n) : "memory")

template<typename F>
__device__ __forceinline__ void cvt_tf32(F& f) {
#pragma unroll
    for (int i = 0; i < f.num_elements; ++i) f.x[i] = wmma::__float_to_tf32(f.x[i]);
}

// ---------------------------------------------------------------------------
// Pack Wq/Wk/Wv (H,E,Dh) -> Wqkv (E, 3E) f32; biases -> g_bqkv
// ---------------------------------------------------------------------------
__global__ void pack_qkv_kernel(const float* __restrict__ Wq, const float* __restrict__ Wk,
                                const float* __restrict__ Wv, const float* __restrict__ bq,
                                const float* __restrict__ bk, const float* __restrict__ bv)
{
    int idx = blockIdx.x * blockDim.x + threadIdx.x;
    if (idx < EMB * N3E) {
        int n = idx % N3E, e = idx / N3E;
        int proj = n / EMB, hd = n % EMB;
        const float* W = (proj == 0) ? Wq : (proj == 1) ? Wk : Wv;
        g_wqkv[idx] = W[(size_t)(hd >> 6) * EMB * DHD + (size_t)e * DHD + (hd & 63)];
    }
    if (idx < N3E) {
        int proj = idx / EMB, hd = idx % EMB;
        const float* bb = (proj == 0) ? bq : (proj == 1) ? bk : bv;
        g_bqkv[idx] = bb[hd];
    }
}

// ---------------------------------------------------------------------------
// TF32 WMMA GEMM, cp.async 3-stage. CTA 128x128, BK=32, 128 thr (2x2 warps),
// warp tile 64x64 (4x4 m16n16k8 frags). A [M][K] f32, B [K][N] f32.
// smem/stage: A 128x36 f32 (18432 B) | B 32x132 f32 (16896 B) = 35328 B.
// MODE: 0 = bias; 1 = bias+res; 2 = relu(bias)
// ---------------------------------------------------------------------------
#define A_ST  36
#define B_ST  132
#define STG   35328
#define GEMM_SMEM (3 * STG)

__device__ __forceinline__ void issue_tile(uint32_t sbase,
    const float* __restrict__ A, const float* __restrict__ B,
    int K, int N, int m0, int n0, int kt, int tid)
{
    // A: thread t -> row t, 32 f32 = 8 x 16B
    const float* pa = A + (size_t)(m0 + tid) * K + kt;
    uint32_t da = sbase + tid * (A_ST * 4);
#pragma unroll
    for (int i = 0; i < 8; ++i) CP_ASYNC(da + i * 16, pa + i * 4);
    // B: thread t -> row t>>2, col block (t&3)*32, 8 x 16B
    int br = tid >> 2, bc = tid & 3;
    const float* pb = B + (size_t)(kt + br) * N + n0 + bc * 32;
    uint32_t db = sbase + 18432 + br * (B_ST * 4) + bc * 128;
#pragma unroll
    for (int i = 0; i < 8; ++i) CP_ASYNC(db + i * 16, pb + i * 4);
}

template<int MODE>
__global__ __launch_bounds__(128)
void tgemm(const float* __restrict__ A, const float* __restrict__ B,
           const float* __restrict__ bias, const float* __restrict__ res,
           float* __restrict__ C, int M, int N, int K)
{
    extern __shared__ char smem[];
    const uint32_t sb = smem_u32(smem);
    const int tid = threadIdx.x;
    const int wid = tid >> 5;
    const int wm = wid >> 1, wn = wid & 1;
    const int bx = blockIdx.x, by = blockIdx.y;
    const int m0 = by * 128, n0 = bx * 128;
    const int NT = K / 32;

    wmma::fragment<wmma::accumulator, 16, 16, 8, float> acc[4][4];
#pragma unroll
    for (int i = 0; i < 4; ++i)
#pragma unroll
        for (int j = 0; j < 4; ++j) wmma::fill_fragment(acc[i][j], 0.f);

#pragma unroll
    for (int s = 0; s < 3; ++s) {
        issue_tile(sb + s * STG, A, B, K, N, m0, n0, s * 32, tid);
        CP_COMMIT();
    }

    for (int t = 0; t < NT; ++t) {
        CP_WAIT(2);
        __syncthreads();

        const int buf = t % 3;
        const float* As = (const float*)(smem + buf * STG);
        const float* Bs = (const float*)(smem + buf * STG + 18432);

#pragma unroll
        for (int ks = 0; ks < 4; ++ks) {
            wmma::fragment<wmma::matrix_a, 16, 16, 8, wmma::precision::tf32, wmma::row_major> fa[4];
#pragma unroll
            for (int i = 0; i < 4; ++i) {
                wmma::load_matrix_sync(fa[i], As + (wm * 64 + i * 16) * A_ST + ks * 8, A_ST);
                cvt_tf32(fa[i]);
            }
#pragma unroll
            for (int j = 0; j < 4; ++j) {
                wmma::fragment<wmma::matrix_b, 16, 16, 8, wmma::precision::tf32, wmma::row_major> fb;
                wmma::load_matrix_sync(fb, Bs + (ks * 8) * B_ST + wn * 64 + j * 16, B_ST);
                cvt_tf32(fb);
#pragma unroll
                for (int i = 0; i < 4; ++i)
                    wmma::mma_sync(acc[i][j], fa[i], fb, acc[i][j]);
            }
        }

        __syncthreads();
        if (t + 3 < NT)
            issue_tile(sb + buf * STG, A, B, K, N, m0, n0, (t + 3) * 32, tid);
        CP_COMMIT();
    }

    CP_WAIT(0);
    __syncthreads();

    // stage accumulators to smem (per-warp 64x68 f32), then fused stores
    float* Cs = (float*)smem;
    float* wbase = Cs + wid * 4352;
#pragma unroll
    for (int i = 0; i < 4; ++i)
#pragma unroll
        for (int j = 0; j < 4; ++j)
            wmma::store_matrix_sync(wbase + (i * 16) * 68 + j * 16, acc[i][j], 68,
                                    wmma::mem_row_major);
    __syncthreads();

    {
        const int m = m0 + tid;
        const float* bp = bias + n0;
        const float* rp = (MODE == 1) ? (res + (size_t)m * N + n0) : nullptr;
#pragma unroll 8
        for (int cb = 0; cb < 128; cb += 4) {
            int w = ((tid >> 6) << 1) | (cb >> 6);
            const float* sp = Cs + w * 4352 + (tid & 63) * 68 + (cb & 63);
            float4 v = *(const float4*)sp;
            float4 bi = *(const float4*)(bp + cb);
            v.x += bi.x; v.y += bi.y; v.z += bi.z; v.w += bi.w;
            if (MODE == 1) {
                float4 rr = *(const float4*)(rp + cb);
                v.x += rr.x; v.y += rr.y; v.z += rr.z; v.w += rr.w;
            }
            if (MODE == 2) {
                v.x = fmaxf(v.x, 0.f); v.y = fmaxf(v.y, 0.f);
                v.z = fmaxf(v.z, 0.f); v.w = fmaxf(v.w, 0.f);
            }
            *(float4*)&C[(size_t)m * N + n0 + cb] = v;
        }
    }
}

// ---------------------------------------------------------------------------
// LayerNorm
// ---------------------------------------------------------------------------
__device__ __forceinline__ float block_sum_1024(float v, float* red)
{
#pragma unroll
    for (int o = 16; o; o >>= 1) v += __shfl_xor_sync(0xffffffffu, v, o);
    int w = threadIdx.x >> 5;
    if ((threadIdx.x & 31) == 0) red[w] = v;
    __syncthreads();
    if (threadIdx.x < 32) {
        float t = (threadIdx.x < 8) ? red[threadIdx.x] : 0.f;
#pragma unroll
        for (int o = 4; o; o >>= 1) t += __shfl_xor_sync(0xffffffffu, t, o);
        if (threadIdx.x == 0) red[0] = t;
    }
    __syncthreads();
    float r = red[0];
    __syncthreads();
    return r;
}

__global__ __launch_bounds__(256)
void layernorm_kernel(const float* __restrict__ in, const float* __restrict__ g,
                      const float* __restrict__ beta, float* __restrict__ out)
{
    __shared__ float red[8];
    const int row = blockIdx.x;
    const int tid = threadIdx.x;
    float4 v = ((const float4*)(in + (size_t)row * EMB))[tid];
    float mean = block_sum_1024(v.x + v.y + v.z + v.w, red) * (1.f / EMB);
    float dx = v.x - mean, dy = v.y - mean, dz = v.z - mean, dw = v.w - mean;
    float var = block_sum_1024(dx * dx + dy * dy + dz * dz + dw * dw, red) * (1.f / EMB);
    float rstd = rsqrtf(var + 1e-5f);
    float4 gv = ((const float4*)g)[tid];
    float4 bv = ((const float4*)beta)[tid];
    float4 o;
    o.x = dx * rstd * gv.x + bv.x;
    o.y = dy * rstd * gv.y + bv.y;
    o.z = dz * rstd * gv.z + bv.z;
    o.w = dw * rstd * gv.w + bv.w;
    ((float4*)(out + (size_t)row * EMB))[tid] = o;
}

// ---------------------------------------------------------------------------
// TF32 WMMA causal flash attention. CTA = (64 q, head, batch). 256 thr.
// qkv rows of 3072: q @0, k @1024, v @2048 (+ h*64).
// ---------------------------------------------------------------------------
struct ATSmem {
    float Qs[64*68], Ks[64*68], Vs[64*68], Ss[64*68], Ps[64*68], Os[64*68];
    float mrow[64], lrow[64], arow[64];
    float pm[4*65], psum[4*65];
};

__global__ __launch_bounds__(256, 2)
void attn_wmma(const float* __restrict__ qkv, float* __restrict__ z)
{
    extern __shared__ char raw[];
    ATSmem& sm = *reinterpret_cast<ATSmem*>(raw);

    const int qb = blockIdx.x, h = blockIdx.y, b = blockIdx.z;
    const int tid = threadIdx.x, wid = tid >> 5;
    const int wy = wid >> 1, wx = wid & 1;      // 4x2 warp grid, 16x32 tiles
    const int r = tid >> 2, sg = tid & 3, c0 = sg * 16;
    const size_t rs = N3E;

    // load Q (scaled), zero O
    {
        const float* qp = qkv + (size_t)(b * LSEQ + qb * 64 + r) * rs + h * 64 + c0;
#pragma unroll
        for (int i = 0; i < 4; ++i) {
            float4 v = *(const float4*)(qp + i * 4);
            v.x *= 0.125f; v.y *= 0.125f; v.z *= 0.125f; v.w *= 0.125f;
            *(float4*)&sm.Qs[r*68 + c0 + i*4] = v;
            *(float4*)&sm.Os[r*68 + c0 + i*4] = make_float4(0.f, 0.f, 0.f, 0.f);
        }
    }
    if (tid < 64) { sm.mrow[tid] = -1e30f; sm.lrow[tid] = 0.f; }

    for (int kb = 0; kb <= qb; ++kb) {
        __syncthreads();
        {
            const float* kp = qkv + (size_t)(b * LSEQ + kb * 64 + r) * rs + EMB + h * 64 + c0;
            const float* vp = kp + EMB;
#pragma unroll
            for (int i = 0; i < 4; ++i) {
                *(float4*)&sm.Ks[r*68 + c0 + i*4] = *(const float4*)(kp + i * 4);
                *(float4*)&sm.Vs[r*68 + c0 + i*4] = *(const float4*)(vp + i * 4);
            }
        }
        __syncthreads();

        // S = Q K^T (tf32)
        {
            wmma::fragment<wmma::accumulator, 16, 16, 8, float> s[2];
            wmma::fill_fragment(s[0], 0.f);
            wmma::fill_fragment(s[1], 0.f);
#pragma unroll
            for (int kk = 0; kk < 8; ++kk) {
                wmma::fragment<wmma::matrix_a, 16, 16, 8, wmma::precision::tf32, wmma::row_major> fa;
                wmma::load_matrix_sync(fa, &sm.Qs[(wy*16)*68 + kk*8], 68);
                cvt_tf32(fa);
#pragma unroll
                for (int j = 0; j < 2; ++j) {
                    wmma::fragment<wmma::matrix_b, 16, 16, 8, wmma::precision::tf32, wmma::col_major> fb;
                    wmma::load_matrix_sync(fb, &sm.Ks[(wx*32 + j*16)*68 + kk*8], 68);
                    cvt_tf32(fb);
                    wmma::mma_sync(s[j], fa, fb, s[j]);
                }
            }
            wmma::store_matrix_sync(&sm.Ss[(wy*16)*68 + wx*32],      s[0], 68, wmma::mem_row_major);
            wmma::store_matrix_sync(&sm.Ss[(wy*16)*68 + wx*32 + 16], s[1], 68, wmma::mem_row_major);
        }
        __syncthreads();

        // online softmax, 4 threads/row
        const bool diag = (kb == qb);
        {
            float mx = -1e30f;
#pragma unroll
            for (int c = 0; c < 16; ++c) {
                float sv = sm.Ss[r*68 + c0 + c];
                if (diag && (c0 + c > r)) sv = -1e30f;
                mx = fmaxf(mx, sv);
            }
            sm.pm[sg*65 + r] = mx;
        }
        __syncthreads();
        if (sg == 0) {
            float mo = sm.mrow[r];
            float mn = fmaxf(fmaxf(sm.pm[r], sm.pm[65 + r]),
                             fmaxf(sm.pm[130 + r], sm.pm[195 + r]));
            mn = fmaxf(mn, mo);
            sm.arow[r] = __expf(mo - mn);
            sm.mrow[r] = mn;
        }
        __syncthreads();
        {
            float mn = sm.mrow[r];
            float ps = 0.f;
#pragma unroll
            for (int c = 0; c < 16; ++c) {
                float sv = sm.Ss[r*68 + c0 + c];
                float p = (diag && (c0 + c > r)) ? 0.f : __expf(sv - mn);
                sm.Ps[r*68 + c0 + c] = p;
                ps += p;
            }
            sm.psum[sg*65 + r] = ps;
        }
        __syncthreads();
        if (sg == 0)
            sm.lrow[r] = sm.lrow[r] * sm.arow[r]
                       + sm.psum[r] + sm.psum[65 + r] + sm.psum[130 + r] + sm.psum[195 + r];

        // PV (tf32) -> Ss
        {
            wmma::fragment<wmma::accumulator, 16, 16, 8, float> o[2];
            wmma::fill_fragment(o[0], 0.f);
            wmma::fill_fragment(o[1], 0.f);
#pragma unroll
            for (int kk = 0; kk < 8; ++kk) {
                wmma::fragment<wmma::matrix_a, 16, 16, 8, wmma::precision::tf32, wmma::row_major> pa;
                wmma::load_matrix_sync(pa, &sm.Ps[(wy*16)*68 + kk*8], 68);
                cvt_tf32(pa);
#pragma unroll
                for (int j = 0; j < 2; ++j) {
                    wmma::fragment<wmma::matrix_b, 16, 16, 8, wmma::precision::tf32, wmma::row_major> vb;
                    wmma::load_matrix_sync(vb, &sm.Vs[(kk*8)*68 + wx*32 + j*16], 68);
                    cvt_tf32(vb);
                    wmma::mma_sync(o[j], pa, vb, o[j]);
                }
            }
            wmma::store_matrix_sync(&sm.Ss[(wy*16)*68 + wx*32],      o[0], 68, wmma::mem_row_major);
            wmma::store_matrix_sync(&sm.Ss[(wy*16)*68 + wx*32 + 16], o[1], 68, wmma::mem_row_major);
        }
        __syncthreads();

        // O = O*alpha + PV
        {
            float al = sm.arow[r];
#pragma unroll
            for (int i = 0; i < 4; ++i) {
                float4 ov = *(float4*)&sm.Os[r*68 + c0 + i*4];
                float4 pv = *(const float4*)&sm.Ss[r*68 + c0 + i*4];
                ov.x = ov.x * al + pv.x; ov.y = ov.y * al + pv.y;
                ov.z = ov.z * al + pv.z; ov.w = ov.w * al + pv.w;
                *(float4*)&sm.Os[r*68 + c0 + i*4] = ov;
            }
        }
    }
    __syncthreads();

    // final normalize + store
    {
        float inv = 1.f / sm.lrow[r];
        float* zp = z + (size_t)(b * LSEQ + qb * 64 + r) * EMB + h * 64 + c0;
#pragma unroll
        for (int i = 0; i < 4; ++i) {
            float4 v = *(const float4*)&sm.Os[r*68 + c0 + i*4];
            v.x *= inv; v.y *= inv; v.z *= inv; v.w *= inv;
            *(float4*)(zp + i * 4) = v;
        }
    }
}

// ---------------------------------------------------------------------------
// Launch
// ---------------------------------------------------------------------------
extern "C" void kernel_launch(void* const* d_in, const int* in_sizes, int n_in,
                              void* d_out, int out_size)
{
    const float* x   = (const float*)d_in[0];
    const float* Wq  = (const float*)d_in[2];
    const float* bq  = (const float*)d_in[3];
    const float* Wk  = (const float*)d_in[4];
    const float* bk  = (const float*)d_in[5];
    const float* Wv  = (const float*)d_in[6];
    const float* bv  = (const float*)d_in[7];
    const float* Wo  = (const float*)d_in[8];
    const float* bo  = (const float*)d_in[9];
    const float* W1  = (const float*)d_in[10];
    const float* c1  = (const float*)d_in[11];
    const float* W2  = (const float*)d_in[12];
    const float* c2  = (const float*)d_in[13];
    const float* g1  = (const float*)d_in[14];
    const float* be1 = (const float*)d_in[15];
    const float* g2  = (const float*)d_in[16];
    const float* be2 = (const float*)d_in[17];
    float* out = (float*)d_out;

    float *wqkv, *bqkv, *qkv, *zz, *t1, *hbuf, *ff;
    cudaGetSymbolAddress((void**)&wqkv, g_wqkv);
    cudaGetSymbolAddress((void**)&bqkv, g_bqkv);
    cudaGetSymbolAddress((void**)&qkv,  g_qkv);
    cudaGetSymbolAddress((void**)&zz,   g_z);
    cudaGetSymbolAddress((void**)&t1,   g_t1);
    cudaGetSymbolAddress((void**)&hbuf, g_h);
    cudaGetSymbolAddress((void**)&ff,   g_ff);

    cudaFuncSetAttribute(attn_wmma, cudaFuncAttributeMaxDynamicSharedMemorySize,
                         (int)sizeof(ATSmem));
    cudaFuncSetAttribute(tgemm<0>, cudaFuncAttributeMaxDynamicSharedMemorySize, GEMM_SMEM);
    cudaFuncSetAttribute(tgemm<1>, cudaFuncAttributeMaxDynamicSharedMemorySize, GEMM_SMEM);
    cudaFuncSetAttribute(tgemm<2>, cudaFuncAttributeMaxDynamicSharedMemorySize, GEMM_SMEM);

    // 1. pack QKV weights/biases (only conversion pass left)
    pack_qkv_kernel<<<(EMB * N3E + 255) / 256, 256>>>(Wq, Wk, Wv, bq, bk, bv);

    // 2. qkv = x @ Wqkv + b
    tgemm<0><<<dim3(N3E / 128, MR / 128), 128, GEMM_SMEM>>>(
        x, wqkv, bqkv, nullptr, qkv, MR, N3E, EMB);

    // 3. attention -> z
    attn_wmma<<<dim3(LSEQ / 64, HN, BSZ), 256, sizeof(ATSmem)>>>(qkv, zz);

    // 4. t1 = z @ Wo + bo + x
    tgemm<1><<<dim3(EMB / 128, MR / 128), 128, GEMM_SMEM>>>(
        zz, Wo, bo, x, t1, MR, EMB, EMB);

    // 5. h = LN1(t1)
    layernorm_kernel<<<MR, 256>>>(t1, g1, be1, hbuf);

    // 6. ff = relu(h @ W1 + c1)
    tgemm<2><<<dim3(DFF / 128, MR / 128), 128, GEMM_SMEM>>>(
        hbuf, W1, c1, nullptr, ff, MR, DFF, EMB);

    // 7. t1 = ff @ W2 + c2 + h
    tgemm<1><<<dim3(EMB / 128, MR / 128), 128, GEMM_SMEM>>>(
        ff, W2, c2, hbuf, t1, MR, EMB, DFF);

    // 8. out = LN2(t1)
    layernorm_kernel<<<MR, 256>>>(t1, g2, be2, out);
}

// round 17
// speedup vs baseline: 1.1546x; 1.0869x over previous
#include <cuda_runtime.h>
#include <cuda_bf16.h>
#include <mma.h>
#include <math.h>
#include <stdint.h>

using namespace nvcuda;

#define BSZ  2
#define LSEQ 2048
#define EMB  1024
#define HN   16
#define DHD  64
#define DFF  4096
#define MR   (BSZ*LSEQ)
#define N3E  (3*EMB)

// ---------------------------------------------------------------------------
// Scratch
// ---------------------------------------------------------------------------
__device__ float g_bqkv[N3E];
__device__ float g_q  [(size_t)MR * EMB];
__device__ float g_t1 [(size_t)MR * EMB];
__device__ float g_h  [(size_t)MR * EMB];

__device__ __nv_bfloat16 g_kh [(size_t)MR * EMB], g_kl [(size_t)MR * EMB];
__device__ __nv_bfloat16 g_vh [(size_t)MR * EMB], g_vl [(size_t)MR * EMB];
__device__ __nv_bfloat16 g_xh [(size_t)MR * EMB], g_xl [(size_t)MR * EMB];
__device__ __nv_bfloat16 g_zh [(size_t)MR * EMB], g_zl [(size_t)MR * EMB];
__device__ __nv_bfloat16 g_hh [(size_t)MR * EMB], g_hl [(size_t)MR * EMB];
__device__ __nv_bfloat16 g_ffh[(size_t)MR * DFF], g_ffl[(size_t)MR * DFF];
__device__ __nv_bfloat16 g_wqkvh[(size_t)EMB * N3E], g_wqkvl[(size_t)EMB * N3E];
__device__ __nv_bfloat16 g_woh[(size_t)EMB * EMB],  g_wol[(size_t)EMB * EMB];
__device__ __nv_bfloat16 g_w1h[(size_t)EMB * DFF],  g_w1l[(size_t)EMB * DFF];
__device__ __nv_bfloat16 g_w2h[(size_t)DFF * EMB],  g_w2l[(size_t)DFF * EMB];

// ---------------------------------------------------------------------------
// helpers
// ---------------------------------------------------------------------------
__device__ __forceinline__ uint32_t smem_u32(const void* p) {
    uint32_t a;
    asm("{ .reg .u64 t; cvta.to.shared.u64 t, %1; cvt.u32.u64 %0, t; }" : "=r"(a) : "l"(p));
    return a;
}
#define CP_ASYNC(dst, src) asm volatile("cp.async.cg.shared.global [%0], [%1], 16;" :: "r"(dst), "l"(src))
#define CP_COMMIT()        asm volatile("cp.async.commit_group;" ::: "memory")
#define CP_WAIT(n)         asm volatile("cp.async.wait_group %0;" :: "n"(n) : "memory")

__device__ __forceinline__ void split2(float v, __nv_bfloat16& h, __nv_bfloat16& l) {
    h = __float2bfloat16(v);
    l = __float2bfloat16(v - __bfloat162float(h));
}

// ---------------------------------------------------------------------------
// fp32 -> bf16 hi/lo split (elementwise)
// ---------------------------------------------------------------------------
__global__ void split_kernel(const float* __restrict__ src, __nv_bfloat16* __restrict__ h,
                             __nv_bfloat16* __restrict__ l, int n4)
{
    int i = blockIdx.x * blockDim.x + threadIdx.x;
    if (i >= n4) return;
    float4 v = ((const float4*)src)[i];
    __nv_bfloat162 h01, h23, l01, l23;
    split2(v.x, h01.x, l01.x); split2(v.y, h01.y, l01.y);
    split2(v.z, h23.x, l23.x); split2(v.w, h23.y, l23.y);
    uint2 hv, lv;
    hv.x = *(uint32_t*)&h01; hv.y = *(uint32_t*)&h23;
    lv.x = *(uint32_t*)&l01; lv.y = *(uint32_t*)&l23;
    ((uint2*)h)[i] = hv;
    ((uint2*)l)[i] = lv;
}

__global__ void pack_qkv_split(const float* __restrict__ Wq, const float* __restrict__ Wk,
                               const float* __restrict__ Wv, const float* __restrict__ bq,
                               const float* __restrict__ bk, const float* __restrict__ bv)
{
    int idx = blockIdx.x * blockDim.x + threadIdx.x;
    if (idx < EMB * N3E) {
        int n = idx % N3E, e = idx / N3E;
        int proj = n / EMB, hd = n % EMB;
        const float* W = (proj == 0) ? Wq : (proj == 1) ? Wk : Wv;
        float v = W[(size_t)(hd >> 6) * EMB * DHD + (size_t)e * DHD + (hd & 63)];
        __nv_bfloat16 h, l; split2(v, h, l);
        g_wqkvh[idx] = h; g_wqkvl[idx] = l;
    }
    if (idx < N3E) {
        int proj = idx / EMB, hd = idx % EMB;
        const float* bb = (proj == 0) ? bq : (proj == 1) ? bk : bv;
        g_bqkv[idx] = bb[hd];
    }
}

// ---------------------------------------------------------------------------
// bf16x3 WMMA GEMM, cp.async 3-stage, 512 threads (16 warps, 4x4),
// CTA tile 128x256, warp tile 32x64, BK=32.
// smem/stage: AH 128x40x2=10240 | AL 10240 | BH 32x264x2=16896 | BL 16896
// stage = 54272 B; 3 stages = 162816 B. Epilogue staging 16x(32x68)x4=139264 B.
// MODE: 1 = f32 C = acc+bias+res; 2 = bf16 hi/lo split of relu(acc+bias);
//       3 = qkv: proj0 -> f32 C, proj1 -> Chi/Clo, proj2 -> Ch2/Cl2 (width 1024)
// ---------------------------------------------------------------------------
#define AH_OFF 0
#define AL_OFF 10240
#define BH_OFF 20480
#define BL_OFF 37376
#define STG    54272
#define GEMM_SMEM (3 * STG)

__device__ __forceinline__ void issue_tile(uint32_t sbase,
    const __nv_bfloat16* __restrict__ Ah, const __nv_bfloat16* __restrict__ Al,
    const __nv_bfloat16* __restrict__ Bh, const __nv_bfloat16* __restrict__ Bl,
    int K, int N, int m0, int n0, int kt, int tid)
{
    if (tid < 256) {
        // A: warps 0-7. thread: buf = tid>>7 (0=hi,1=lo), row = tid&127, 32 bf16
        const int buf = tid >> 7, tl = tid & 127;
        const __nv_bfloat16* src = (buf ? Al : Ah) + (size_t)(m0 + tl) * K + kt;
        uint32_t dst = sbase + (buf ? AL_OFF : AH_OFF) + tl * 80;
#pragma unroll
        for (int i = 0; i < 4; ++i) CP_ASYNC(dst + i * 16, src + i * 8);
    } else {
        // B: warps 8-15. thread: buf, row = tl>>2 (0..31), colblk = (tl&3)*64
        const int t2 = tid - 256, buf = t2 >> 7, tl = t2 & 127;
        const int row = tl >> 2, cb = (tl & 3) * 64;
        const __nv_bfloat16* src = (buf ? Bl : Bh) + (size_t)(kt + row) * N + n0 + cb;
        uint32_t dst = sbase + (buf ? BL_OFF : BH_OFF) + row * 528 + cb * 2;
#pragma unroll
        for (int i = 0; i < 8; ++i) CP_ASYNC(dst + i * 16, src + i * 8);
    }
}

template<int MODE>
__global__ __launch_bounds__(512)
void bgemm(const __nv_bfloat16* __restrict__ Ah, const __nv_bfloat16* __restrict__ Al,
           const __nv_bfloat16* __restrict__ Bh, const __nv_bfloat16* __restrict__ Bl,
           const float* __restrict__ bias, const float* __restrict__ res,
           float* __restrict__ C, __nv_bfloat16* __restrict__ Chi,
           __nv_bfloat16* __restrict__ Clo, __nv_bfloat16* __restrict__ Ch2,
           __nv_bfloat16* __restrict__ Cl2, int M, int N, int K)
{
    extern __shared__ char smem[];
    const uint32_t sb = smem_u32(smem);
    const int tid = threadIdx.x;
    const int wid = tid >> 5;
    const int wm = wid >> 2, wn = wid & 3;       // 4x4 warp grid, 32x64 tiles
    const int bx = blockIdx.x, by = blockIdx.y;
    const int m0 = by * 128, n0 = bx * 256;
    const int NT = K / 32;

    wmma::fragment<wmma::accumulator, 16, 16, 16, float> acc[2][4];
#pragma unroll
    for (int i = 0; i < 2; ++i)
#pragma unroll
        for (int j = 0; j < 4; ++j) wmma::fill_fragment(acc[i][j], 0.f);

#pragma unroll
    for (int s = 0; s < 3; ++s) {
        issue_tile(sb + s * STG, Ah, Al, Bh, Bl, K, N, m0, n0, s * 32, tid);
        CP_COMMIT();
    }

    for (int t = 0; t < NT; ++t) {
        CP_WAIT(2);
        __syncthreads();

        const int buf = t % 3;
        const __nv_bfloat16* AHs = (const __nv_bfloat16*)(smem + buf * STG + AH_OFF);
        const __nv_bfloat16* ALs = (const __nv_bfloat16*)(smem + buf * STG + AL_OFF);
        const __nv_bfloat16* BHs = (const __nv_bfloat16*)(smem + buf * STG + BH_OFF);
        const __nv_bfloat16* BLs = (const __nv_bfloat16*)(smem + buf * STG + BL_OFF);

#pragma unroll
        for (int ks = 0; ks < 2; ++ks) {
            wmma::fragment<wmma::matrix_a, 16, 16, 16, __nv_bfloat16, wmma::row_major> fah[2], fal[2];
#pragma unroll
            for (int i = 0; i < 2; ++i) {
                int off = (wm * 32 + i * 16) * 40 + ks * 16;
                wmma::load_matrix_sync(fah[i], AHs + off, 40);
                wmma::load_matrix_sync(fal[i], ALs + off, 40);
            }
#pragma unroll
            for (int j = 0; j < 4; ++j) {
                wmma::fragment<wmma::matrix_b, 16, 16, 16, __nv_bfloat16, wmma::row_major> fbh, fbl;
                int off = (ks * 16) * 264 + wn * 64 + j * 16;
                wmma::load_matrix_sync(fbh, BHs + off, 264);
                wmma::load_matrix_sync(fbl, BLs + off, 264);
#pragma unroll
                for (int i = 0; i < 2; ++i) {
                    wmma::mma_sync(acc[i][j], fah[i], fbh, acc[i][j]);
                    wmma::mma_sync(acc[i][j], fah[i], fbl, acc[i][j]);
                    wmma::mma_sync(acc[i][j], fal[i], fbh, acc[i][j]);
                }
            }
        }

        __syncthreads();
        if (t + 3 < NT)
            issue_tile(sb + buf * STG, Ah, Al, Bh, Bl, K, N, m0, n0, (t + 3) * 32, tid);
        CP_COMMIT();
    }

    CP_WAIT(0);
    __syncthreads();

    // stage accumulators: per-warp 32x68 f32 region (2176 floats)
    float* Cs = (float*)smem;
    float* wbase = Cs + wid * 2176;
#pragma unroll
    for (int i = 0; i < 2; ++i)
#pragma unroll
        for (int j = 0; j < 4; ++j)
            wmma::store_matrix_sync(wbase + (i * 16) * 68 + j * 16, acc[i][j], 68,
                                    wmma::mem_row_major);
    __syncthreads();

    // fused output: thread t -> row t>>2, col block (t&3)*64 (64 cols)
    {
        const int row = tid >> 2;
        const int cb = (tid & 3) * 64;
        const int m = m0 + row;
        const int w = (row >> 5) * 4 + (cb >> 6);
        const float* sp0 = Cs + w * 2176 + (row & 31) * 68;
        const float* bp = bias + n0 + cb;
        const float* rp = (MODE == 1) ? (res + (size_t)m * N + n0 + cb) : nullptr;
        const int proj = (MODE == 3) ? (n0 >> 10) : 0;
        const int colb = (MODE == 3) ? ((n0 & 1023) + cb) : 0;
#pragma unroll 4
        for (int cc = 0; cc < 64; cc += 4) {
            float4 v = *(const float4*)(sp0 + cb % 64 + cc);   // col within warp tile = cc
            float4 bi = *(const float4*)(bp + cc);
            v.x += bi.x; v.y += bi.y; v.z += bi.z; v.w += bi.w;
            if (MODE == 1) {
                float4 rr = *(const float4*)(rp + cc);
                v.x += rr.x; v.y += rr.y; v.z += rr.z; v.w += rr.w;
            }
            if (MODE == 2) {
                v.x = fmaxf(v.x, 0.f); v.y = fmaxf(v.y, 0.f);
                v.z = fmaxf(v.z, 0.f); v.w = fmaxf(v.w, 0.f);
            }
            if (MODE == 2 || (MODE == 3 && proj != 0)) {
                __nv_bfloat162 h01, h23, l01, l23;
                split2(v.x, h01.x, l01.x); split2(v.y, h01.y, l01.y);
                split2(v.z, h23.x, l23.x); split2(v.w, h23.y, l23.y);
                uint2 hv, lv;
                hv.x = *(uint32_t*)&h01; hv.y = *(uint32_t*)&h23;
                lv.x = *(uint32_t*)&l01; lv.y = *(uint32_t*)&l23;
                if (MODE == 2) {
                    *(uint2*)&Chi[(size_t)m * N + n0 + cb + cc] = hv;
                    *(uint2*)&Clo[(size_t)m * N + n0 + cb + cc] = lv;
                } else {
                    __nv_bfloat16* H = (proj == 1) ? Chi : Ch2;
                    __nv_bfloat16* L = (proj == 1) ? Clo : Cl2;
                    *(uint2*)&H[(size_t)m * 1024 + colb + cc] = hv;
                    *(uint2*)&L[(size_t)m * 1024 + colb + cc] = lv;
                }
            } else if (MODE == 3) {
                *(float4*)&C[(size_t)m * 1024 + colb + cc] = v;
            } else {
                *(float4*)&C[(size_t)m * N + n0 + cb + cc] = v;
            }
        }
    }
}

// ---------------------------------------------------------------------------
// LayerNorm (optional split output)
// ---------------------------------------------------------------------------
__device__ __forceinline__ float block_sum_1024(float v, float* red)
{
#pragma unroll
    for (int o = 16; o; o >>= 1) v += __shfl_xor_sync(0xffffffffu, v, o);
    int w = threadIdx.x >> 5;
    if ((threadIdx.x & 31) == 0) red[w] = v;
    __syncthreads();
    if (threadIdx.x < 32) {
        float t = (threadIdx.x < 8) ? red[threadIdx.x] : 0.f;
#pragma unroll
        for (int o = 4; o; o >>= 1) t += __shfl_xor_sync(0xffffffffu, t, o);
        if (threadIdx.x == 0) red[0] = t;
    }
    __syncthreads();
    float r = red[0];
    __syncthreads();
    return r;
}

template<bool SPLIT>
__global__ __launch_bounds__(256)
void layernorm_kernel(const float* __restrict__ in, const float* __restrict__ g,
                      const float* __restrict__ beta, float* __restrict__ out,
                      __nv_bfloat16* __restrict__ oh, __nv_bfloat16* __restrict__ ol)
{
    __shared__ float red[8];
    const int row = blockIdx.x;
    const int tid = threadIdx.x;
    float4 v = ((const float4*)(in + (size_t)row * EMB))[tid];
    float mean = block_sum_1024(v.x + v.y + v.z + v.w, red) * (1.f / EMB);
    float dx = v.x - mean, dy = v.y - mean, dz = v.z - mean, dw = v.w - mean;
    float var = block_sum_1024(dx * dx + dy * dy + dz * dz + dw * dw, red) * (1.f / EMB);
    float rstd = rsqrtf(var + 1e-5f);
    float4 gv = ((const float4*)g)[tid];
    float4 bv = ((const float4*)beta)[tid];
    float4 o;
    o.x = dx * rstd * gv.x + bv.x;
    o.y = dy * rstd * gv.y + bv.y;
    o.z = dz * rstd * gv.z + bv.z;
    o.w = dw * rstd * gv.w + bv.w;
    ((float4*)(out + (size_t)row * EMB))[tid] = o;
    if (SPLIT) {
        __nv_bfloat162 h01, h23, l01, l23;
        split2(o.x, h01.x, l01.x); split2(o.y, h01.y, l01.y);
        split2(o.z, h23.x, l23.x); split2(o.w, h23.y, l23.y);
        uint2 hv, lv;
        hv.x = *(uint32_t*)&h01; hv.y = *(uint32_t*)&h23;
        lv.x = *(uint32_t*)&l01; lv.y = *(uint32_t*)&l23;
        ((uint2*)(oh + (size_t)row * EMB))[tid] = hv;
        ((uint2*)(ol + (size_t)row * EMB))[tid] = lv;
    }
}

// ---------------------------------------------------------------------------
// WMMA causal flash attention (R12, unchanged — measured good)
// ---------------------------------------------------------------------------
struct ASmem {
    __nv_bfloat16 Qh[64*72], Ql[64*72], Kh[64*72], Kl[64*72];
    __nv_bfloat16 Vh[64*72], Vl[64*72], Ph[64*72], Pl[64*72];
    float Ss[64*72];
    float Os[64*72];
    float mrow[64], lrow[64], arow[64];
    float pm[4*65], ps[4*65];
};

__global__ __launch_bounds__(256, 2)
void attn_wmma(const float* __restrict__ q,
               const __nv_bfloat16* __restrict__ kh, const __nv_bfloat16* __restrict__ kl,
               const __nv_bfloat16* __restrict__ vh, const __nv_bfloat16* __restrict__ vl,
               __nv_bfloat16* __restrict__ zh, __nv_bfloat16* __restrict__ zl)
{
    extern __shared__ char raw[];
    ASmem& sm = *reinterpret_cast<ASmem*>(raw);

    const int qb = blockIdx.x, h = blockIdx.y, b = blockIdx.z;
    const int tid = threadIdx.x, wid = tid >> 5;
    const int wy = wid >> 1, wx = wid & 1;
    const int r = tid >> 2, sg = tid & 3, c0 = sg * 16;

    {
        const float* qp = q + (size_t)(b * LSEQ + qb * 64 + r) * EMB + h * 64 + c0;
#pragma unroll
        for (int i = 0; i < 4; ++i) {
            float4 v = *(const float4*)(qp + i * 4);
            v.x *= 0.125f; v.y *= 0.125f; v.z *= 0.125f; v.w *= 0.125f;
            split2(v.x, sm.Qh[r*72 + c0 + i*4 + 0], sm.Ql[r*72 + c0 + i*4 + 0]);
            split2(v.y, sm.Qh[r*72 + c0 + i*4 + 1], sm.Ql[r*72 + c0 + i*4 + 1]);
            split2(v.z, sm.Qh[r*72 + c0 + i*4 + 2], sm.Ql[r*72 + c0 + i*4 + 2]);
            split2(v.w, sm.Qh[r*72 + c0 + i*4 + 3], sm.Ql[r*72 + c0 + i*4 + 3]);
            *(float4*)&sm.Os[r*72 + c0 + i*4] = make_float4(0.f, 0.f, 0.f, 0.f);
        }
    }
    if (tid < 64) { sm.mrow[tid] = -1e30f; sm.lrow[tid] = 0.f; }

    for (int kb = 0; kb <= qb; ++kb) {
        __syncthreads();
        {
            size_t go = (size_t)(b * LSEQ + kb * 64 + r) * EMB + h * 64 + c0;
            *(uint4*)&sm.Kh[r*72 + c0]     = *(const uint4*)(kh + go);
            *(uint4*)&sm.Kh[r*72 + c0 + 8] = *(const uint4*)(kh + go + 8);
            *(uint4*)&sm.Kl[r*72 + c0]     = *(const uint4*)(kl + go);
            *(uint4*)&sm.Kl[r*72 + c0 + 8] = *(const uint4*)(kl + go + 8);
            *(uint4*)&sm.Vh[r*72 + c0]     = *(const uint4*)(vh + go);
            *(uint4*)&sm.Vh[r*72 + c0 + 8] = *(const uint4*)(vh + go + 8);
            *(uint4*)&sm.Vl[r*72 + c0]     = *(const uint4*)(vl + go);
            *(uint4*)&sm.Vl[r*72 + c0 + 8] = *(const uint4*)(vl + go + 8);
        }
        __syncthreads();

        {
            wmma::fragment<wmma::accumulator, 16, 16, 16, float> s[2];
            wmma::fill_fragment(s[0], 0.f);
            wmma::fill_fragment(s[1], 0.f);
#pragma unroll
            for (int kk = 0; kk < 4; ++kk) {
                wmma::fragment<wmma::matrix_a, 16, 16, 16, __nv_bfloat16, wmma::row_major> fah, fal;
                wmma::load_matrix_sync(fah, &sm.Qh[(wy*16)*72 + kk*16], 72);
                wmma::load_matrix_sync(fal, &sm.Ql[(wy*16)*72 + kk*16], 72);
#pragma unroll
                for (int j = 0; j < 2; ++j) {
                    wmma::fragment<wmma::matrix_b, 16, 16, 16, __nv_bfloat16, wmma::col_major> fbh, fbl;
                    wmma::load_matrix_sync(fbh, &sm.Kh[(wx*32 + j*16)*72 + kk*16], 72);
                    wmma::load_matrix_sync(fbl, &sm.Kl[(wx*32 + j*16)*72 + kk*16], 72);
                    wmma::mma_sync(s[j], fah, fbh, s[j]);
                    wmma::mma_sync(s[j], fah, fbl, s[j]);
                    wmma::mma_sync(s[j], fal, fbh, s[j]);
                }
            }
            wmma::store_matrix_sync(&sm.Ss[(wy*16)*72 + wx*32],      s[0], 72, wmma::mem_row_major);
            wmma::store_matrix_sync(&sm.Ss[(wy*16)*72 + wx*32 + 16], s[1], 72, wmma::mem_row_major);
        }
        __syncthreads();

        const bool diag = (kb == qb);
        {
            float mx = -1e30f;
#pragma unroll
            for (int c = 0; c < 16; ++c) {
                float sv = sm.Ss[r*72 + c0 + c];
                if (diag && (c0 + c > r)) sv = -1e30f;
                mx = fmaxf(mx, sv);
            }
            sm.pm[sg*65 + r] = mx;
        }
        __syncthreads();
        if (sg == 0) {
            float mo = sm.mrow[r];
            float mn = fmaxf(fmaxf(sm.pm[r], sm.pm[65 + r]),
                             fmaxf(sm.pm[130 + r], sm.pm[195 + r]));
            mn = fmaxf(mn, mo);
            sm.arow[r] = __expf(mo - mn);
            sm.mrow[r] = mn;
        }
        __syncthreads();
        {
            float mn = sm.mrow[r];
            float psum = 0.f;
#pragma unroll
            for (int c = 0; c < 16; ++c) {
                float sv = sm.Ss[r*72 + c0 + c];
                float p = (diag && (c0 + c > r)) ? 0.f : __expf(sv - mn);
                split2(p, sm.Ph[r*72 + c0 + c], sm.Pl[r*72 + c0 + c]);
                psum += p;
            }
            sm.ps[sg*65 + r] = psum;
        }
        __syncthreads();
        if (sg == 0)
            sm.lrow[r] = sm.lrow[r] * sm.arow[r]
                       + sm.ps[r] + sm.ps[65 + r] + sm.ps[130 + r] + sm.ps[195 + r];

        {
            wmma::fragment<wmma::accumulator, 16, 16, 16, float> o[2];
            wmma::fill_fragment(o[0], 0.f);
            wmma::fill_fragment(o[1], 0.f);
#pragma unroll
            for (int kk = 0; kk < 4; ++kk) {
                wmma::fragment<wmma::matrix_a, 16, 16, 16, __nv_bfloat16, wmma::row_major> pah, pal;
                wmma::load_matrix_sync(pah, &sm.Ph[(wy*16)*72 + kk*16], 72);
                wmma::load_matrix_sync(pal, &sm.Pl[(wy*16)*72 + kk*16], 72);
#pragma unroll
                for (int j = 0; j < 2; ++j) {
                    wmma::fragment<wmma::matrix_b, 16, 16, 16, __nv_bfloat16, wmma::row_major> vbh, vbl;
                    wmma::load_matrix_sync(vbh, &sm.Vh[(kk*16)*72 + wx*32 + j*16], 72);
                    wmma::load_matrix_sync(vbl, &sm.Vl[(kk*16)*72 + wx*32 + j*16], 72);
                    wmma::mma_sync(o[j], pah, vbh, o[j]);
                    wmma::mma_sync(o[j], pah, vbl, o[j]);
                    wmma::mma_sync(o[j], pal, vbh, o[j]);
                }
            }
            wmma::store_matrix_sync(&sm.Ss[(wy*16)*72 + wx*32],      o[0], 72, wmma::mem_row_major);
            wmma::store_matrix_sync(&sm.Ss[(wy*16)*72 + wx*32 + 16], o[1], 72, wmma::mem_row_major);
        }
        __syncthreads();

        {
            float al = sm.arow[r];
#pragma unroll
            for (int i = 0; i < 4; ++i) {
                float4 ov = *(float4*)&sm.Os[r*72 + c0 + i*4];
                float4 pv = *(const float4*)&sm.Ss[r*72 + c0 + i*4];
                ov.x = ov.x * al + pv.x; ov.y = ov.y * al + pv.y;
                ov.z = ov.z * al + pv.z; ov.w = ov.w * al + pv.w;
                *(float4*)&sm.Os[r*72 + c0 + i*4] = ov;
            }
        }
    }
    __syncthreads();

    {
        float inv = 1.f / sm.lrow[r];
        uint32_t hp[8], lp[8];
#pragma unroll
        for (int cc = 0; cc < 8; ++cc) {
            float v0 = sm.Os[r*72 + c0 + cc*2]     * inv;
            float v1 = sm.Os[r*72 + c0 + cc*2 + 1] * inv;
            __nv_bfloat162 h2, l2;
            split2(v0, h2.x, l2.x);
            split2(v1, h2.y, l2.y);
            hp[cc] = *(uint32_t*)&h2;
            lp[cc] = *(uint32_t*)&l2;
        }
        size_t off = (size_t)(b * LSEQ + qb * 64 + r) * EMB + h * 64 + c0;
        *(uint4*)&zh[off]     = make_uint4(hp[0], hp[1], hp[2], hp[3]);
        *(uint4*)&zh[off + 8] = make_uint4(hp[4], hp[5], hp[6], hp[7]);
        *(uint4*)&zl[off]     = make_uint4(lp[0], lp[1], lp[2], lp[3]);
        *(uint4*)&zl[off + 8] = make_uint4(lp[4], lp[5], lp[6], lp[7]);
    }
}

// ---------------------------------------------------------------------------
// Launch
// ---------------------------------------------------------------------------
extern "C" void kernel_launch(void* const* d_in, const int* in_sizes, int n_in,
                              void* d_out, int out_size)
{
    const float* x   = (const float*)d_in[0];
    const float* Wq  = (const float*)d_in[2];
    const float* bq  = (const float*)d_in[3];
    const float* Wk  = (const float*)d_in[4];
    const float* bk  = (const float*)d_in[5];
    const float* Wv  = (const float*)d_in[6];
    const float* bv  = (const float*)d_in[7];
    const float* Wo  = (const float*)d_in[8];
    const float* bo  = (const float*)d_in[9];
    const float* W1  = (const float*)d_in[10];
    const float* c1  = (const float*)d_in[11];
    const float* W2  = (const float*)d_in[12];
    const float* c2  = (const float*)d_in[13];
    const float* g1  = (const float*)d_in[14];
    const float* be1 = (const float*)d_in[15];
    const float* g2  = (const float*)d_in[16];
    const float* be2 = (const float*)d_in[17];
    float* out = (float*)d_out;

    float *bqkv, *qbuf, *t1, *hbuf;
    __nv_bfloat16 *kh, *kl, *vh, *vl, *xh, *xl, *zh, *zl, *hh, *hl, *ffh, *ffl;
    __nv_bfloat16 *wqh, *wql, *woh, *wol, *w1h, *w1l, *w2h, *w2l;
    cudaGetSymbolAddress((void**)&bqkv, g_bqkv);
    cudaGetSymbolAddress((void**)&qbuf, g_q);
    cudaGetSymbolAddress((void**)&t1,   g_t1);
    cudaGetSymbolAddress((void**)&hbuf, g_h);
    cudaGetSymbolAddress((void**)&kh, g_kh); cudaGetSymbolAddress((void**)&kl, g_kl);
    cudaGetSymbolAddress((void**)&vh, g_vh); cudaGetSymbolAddress((void**)&vl, g_vl);
    cudaGetSymbolAddress((void**)&xh, g_xh); cudaGetSymbolAddress((void**)&xl, g_xl);
    cudaGetSymbolAddress((void**)&zh, g_zh); cudaGetSymbolAddress((void**)&zl, g_zl);
    cudaGetSymbolAddress((void**)&hh, g_hh); cudaGetSymbolAddress((void**)&hl, g_hl);
    cudaGetSymbolAddress((void**)&ffh, g_ffh); cudaGetSymbolAddress((void**)&ffl, g_ffl);
    cudaGetSymbolAddress((void**)&wqh, g_wqkvh); cudaGetSymbolAddress((void**)&wql, g_wqkvl);
    cudaGetSymbolAddress((void**)&woh, g_woh);   cudaGetSymbolAddress((void**)&wol, g_wol);
    cudaGetSymbolAddress((void**)&w1h, g_w1h);   cudaGetSymbolAddress((void**)&w1l, g_w1l);
    cudaGetSymbolAddress((void**)&w2h, g_w2h);   cudaGetSymbolAddress((void**)&w2l, g_w2l);

    cudaFuncSetAttribute(attn_wmma, cudaFuncAttributeMaxDynamicSharedMemorySize,
                         (int)sizeof(ASmem));
    cudaFuncSetAttribute(bgemm<1>, cudaFuncAttributeMaxDynamicSharedMemorySize, GEMM_SMEM);
    cudaFuncSetAttribute(bgemm<2>, cudaFuncAttributeMaxDynamicSharedMemorySize, GEMM_SMEM);
    cudaFuncSetAttribute(bgemm<3>, cudaFuncAttributeMaxDynamicSharedMemorySize, GEMM_SMEM);

    // conversions
    pack_qkv_split<<<(EMB * N3E + 255) / 256, 256>>>(Wq, Wk, Wv, bq, bk, bv);
    split_kernel<<<(EMB * EMB / 4 + 255) / 256, 256>>>(Wo, woh, wol, EMB * EMB / 4);
    split_kernel<<<(EMB * DFF / 4 + 255) / 256, 256>>>(W1, w1h, w1l, EMB * DFF / 4);
    split_kernel<<<(DFF * EMB / 4 + 255) / 256, 256>>>(W2, w2h, w2l, DFF * EMB / 4);
    split_kernel<<<(MR * EMB / 4 + 255) / 256, 256>>>(x, xh, xl, MR * EMB / 4);

    // qkv: q -> f32, k/v -> bf16 hi/lo splits
    bgemm<3><<<dim3(N3E / 256, MR / 128), 512, GEMM_SMEM>>>(
        xh, xl, wqh, wql, bqkv, nullptr, qbuf, kh, kl, vh, vl, MR, N3E, EMB);

    // attention -> zh/zl
    attn_wmma<<<dim3(LSEQ / 64, HN, BSZ), 256, sizeof(ASmem)>>>(
        qbuf, kh, kl, vh, vl, zh, zl);

    // t1 = z @ Wo + bo + x
    bgemm<1><<<dim3(EMB / 256, MR / 128), 512, GEMM_SMEM>>>(
        zh, zl, woh, wol, bo, x, t1, nullptr, nullptr, nullptr, nullptr, MR, EMB, EMB);

    // h = LN1(t1) + split
    layernorm_kernel<true><<<MR, 256>>>(t1, g1, be1, hbuf, hh, hl);

    // ff = relu(h @ W1 + c1) -> ffh/ffl
    bgemm<2><<<dim3(DFF / 256, MR / 128), 512, GEMM_SMEM>>>(
        hh, hl, w1h, w1l, c1, nullptr, nullptr, ffh, ffl, nullptr, nullptr, MR, DFF, EMB);

    // t1 = ff @ W2 + c2 + h
    bgemm<1><<<dim3(EMB / 256, MR / 128), 512, GEMM_SMEM>>>(
        ffh, ffl, w2h, w2l, c2, hbuf, t1, nullptr, nullptr, nullptr, nullptr, MR, EMB, DFF);

    // out = LN2(t1)
    layernorm_kernel<false><<<MR, 256>>>(t1, g2, be2, out, nullptr, nullptr);
}